// round 4
// baseline (speedup 1.0000x reference)
#include <cuda_runtime.h>

#define EPSV   1e-5f
#define DW_THR 4.0f
#define PW_THR 0.001f

// Shapes: B=64, C=128, O=256, H=W=56, HW=3136
__device__ float g_y[64 * 128 * 3136];   // pruned depthwise output [B,C,HW]
__device__ int   g_keep[64 * 128];       // per-(b,c) keep flag
__device__ int   g_idx[64 * 128];        // per-b compacted kept-channel list
__device__ int   g_cnt[64];              // per-b kept count
__device__ int   g_max[64 * 256];        // per-(b,o) max(z) as int bits (z>=0)

// ---------------------------------------------------------------------------
// packed fp32x2 helpers (Blackwell FFMA2)
// ---------------------------------------------------------------------------
__device__ __forceinline__ unsigned long long fma2(unsigned long long a,
                                                   unsigned long long b,
                                                   unsigned long long c) {
    unsigned long long d;
    asm("fma.rn.f32x2 %0, %1, %2, %3;" : "=l"(d) : "l"(a), "l"(b), "l"(c));
    return d;
}
__device__ __forceinline__ unsigned long long pk2(float lo, float hi) {
    unsigned long long d;
    asm("mov.b64 %0, {%1, %2};" : "=l"(d) : "f"(lo), "f"(hi));
    return d;
}
__device__ __forceinline__ float2 upk2(unsigned long long v) {
    float2 r;
    asm("mov.b64 {%0, %1}, %2;" : "=f"(r.x), "=f"(r.y) : "l"(v));
    return r;
}

// ---------------------------------------------------------------------------
// Depthwise 3x3 + bias + BN1 + ReLU + per-(b,c) prune. (unchanged — passing)
// ---------------------------------------------------------------------------
__global__ __launch_bounds__(256) void dw_kernel(
    const float* __restrict__ x,
    const float* __restrict__ dw_w, const float* __restrict__ dw_b,
    const float* __restrict__ g1,  const float* __restrict__ b1,
    const float* __restrict__ m1,  const float* __restrict__ v1)
{
    __shared__ float sx[3136];
    __shared__ float red[8];
    __shared__ float s_bmax;

    const int slice = blockIdx.x;          // b*128 + c
    const int c = slice & 127;
    const float* xs = x + (size_t)slice * 3136;

    const float w0 = dw_w[c * 9 + 0], w1 = dw_w[c * 9 + 1], w2 = dw_w[c * 9 + 2];
    const float w3 = dw_w[c * 9 + 3], w4 = dw_w[c * 9 + 4], w5 = dw_w[c * 9 + 5];
    const float w6 = dw_w[c * 9 + 6], w7 = dw_w[c * 9 + 7], w8 = dw_w[c * 9 + 8];
    const float s = g1[c] * rsqrtf(v1[c] + EPSV);
    const float t = fmaf(dw_b[c] - m1[c], s, b1[c]);

    const int tid = threadIdx.x;

    {
        const float4* x4 = (const float4*)xs;
        float4* s4 = (float4*)sx;
        for (int i = tid; i < 784; i += 256) s4[i] = x4[i];
    }
    __syncthreads();

    float lv[14];
    float mx = 0.f;
    int col = 0, band = 0;
    if (tid < 224) {
        col  = tid % 56;
        band = tid / 56;               // rows band*14 .. band*14+13
        const bool cL = (col > 0), cR = (col < 55);
        const int base = band * 14 * 56 + col;

        float r0c0 = 0.f, r0c1 = 0.f, r0c2 = 0.f;
        if (band > 0) {
            int a = base - 56;
            r0c0 = cL ? sx[a - 1] : 0.f; r0c1 = sx[a]; r0c2 = cR ? sx[a + 1] : 0.f;
        }
        float r1c0 = cL ? sx[base - 1] : 0.f;
        float r1c1 = sx[base];
        float r1c2 = cR ? sx[base + 1] : 0.f;

#pragma unroll
        for (int j = 0; j < 14; j++) {
            int rr = band * 14 + j + 1;
            float r2c0 = 0.f, r2c1 = 0.f, r2c2 = 0.f;
            if (rr < 56) {
                int a = base + (j + 1) * 56;
                r2c0 = cL ? sx[a - 1] : 0.f; r2c1 = sx[a]; r2c2 = cR ? sx[a + 1] : 0.f;
            }
            float acc =        r0c0 * w0;
            acc = fmaf(r0c1, w1, acc); acc = fmaf(r0c2, w2, acc);
            acc = fmaf(r1c0, w3, acc); acc = fmaf(r1c1, w4, acc);
            acc = fmaf(r1c2, w5, acc);
            acc = fmaf(r2c0, w6, acc); acc = fmaf(r2c1, w7, acc);
            acc = fmaf(r2c2, w8, acc);
            float z = fmaxf(fmaf(acc, s, t), 0.f);
            lv[j] = z;
            mx = fmaxf(mx, z);
            r0c0 = r1c0; r0c1 = r1c1; r0c2 = r1c2;
            r1c0 = r2c0; r1c1 = r2c1; r1c2 = r2c2;
        }
    }

    for (int off = 16; off; off >>= 1)
        mx = fmaxf(mx, __shfl_xor_sync(0xffffffffu, mx, off));
    if ((tid & 31) == 0) red[tid >> 5] = mx;
    __syncthreads();
    if (tid == 0) {
        float m = red[0];
#pragma unroll
        for (int i = 1; i < 8; i++) m = fmaxf(m, red[i]);
        s_bmax = m;
        g_keep[slice] = (m >= DW_THR) ? 1 : 0;
    }
    __syncthreads();

    if (s_bmax >= DW_THR && tid < 224) {
        float* yo = g_y + (size_t)slice * 3136 + band * 14 * 56 + col;
#pragma unroll
        for (int j = 0; j < 14; j++) yo[j * 56] = lv[j];
    }
}

// ---------------------------------------------------------------------------
// Per-batch compaction of kept channels + zero g_max (graph-replay safe)
// ---------------------------------------------------------------------------
__global__ void compact_kernel() {
    const int b = blockIdx.x;
    const int tid = threadIdx.x;              // 256 threads
    g_max[b * 256 + tid] = 0;
    __shared__ int wcnt[4];
    if (tid < 128) {
        const int f = g_keep[b * 128 + tid];
        const unsigned bal = __ballot_sync(0xffffffffu, f);
        const int lane = tid & 31, w = tid >> 5;
        const int pre = __popc(bal & ((1u << lane) - 1u));
        if (lane == 0) wcnt[w] = __popc(bal);
        __syncthreads();
        int off = 0;
#pragma unroll
        for (int i = 0; i < 4; i++) if (i < w) off += wcnt[i];
        if (f) g_idx[b * 128 + off + pre] = tid;
        if (tid == 0) g_cnt[b] = wcnt[0] + wcnt[1] + wcnt[2] + wcnt[3];
    } else {
        __syncthreads();
    }
}

// ---------------------------------------------------------------------------
// Pointwise GEMM over compacted K + BN2 + ReLU + per-(b,o) max.
// Tile 128(O) x 128(HW), 8x8 microtile, FFMA2. K-tile = 8 (cnt is small).
// grid = (25 hw-tiles, 2 o-tiles, 64 batches), 256 threads.
// ---------------------------------------------------------------------------
#define KT 8
__global__ __launch_bounds__(256, 3) void pw_kernel(
    const float* __restrict__ pw_w, const float* __restrict__ pw_b,
    const float* __restrict__ g2,  const float* __restrict__ b2,
    const float* __restrict__ m2,  const float* __restrict__ v2,
    float* __restrict__ out)
{
    __shared__ float sW[KT][132];   // [k][o]
    __shared__ float sY[KT][132];   // [k][hw]
    __shared__ int   sidx[KT];

    const int tid = threadIdx.x;
    const int tx = tid & 15;        // hw: 16 threads x 8
    const int ty = tid >> 4;        // o : 16 threads x 8
    const int hwb = blockIdx.x * 128;
    const int ob  = blockIdx.y * 128;
    const int b   = blockIdx.z;

    const bool colok = (hwb + tx * 8) < 3136;   // last tile is 64 wide

    const int cnt = g_cnt[b];
    const int ntiles = (cnt + KT - 1) / KT;

    unsigned long long acc[4][8];
#pragma unroll
    for (int p = 0; p < 4; p++)
#pragma unroll
        for (int q = 0; q < 8; q++) acc[p][q] = 0ull;

    for (int kt = 0; kt < ntiles; kt++) {
        int klim = cnt - kt * KT;
        if (klim > KT) klim = KT;
        const int kstage = (klim + 3) & ~3;

        if (tid < KT) {
            int kk = kt * KT + tid;
            sidx[tid] = (kk < cnt) ? g_idx[b * 128 + kk] : -1;
        }
        __syncthreads();

        // W tile: gather+transpose -> sW[k][o], rows k < kstage
#pragma unroll
        for (int j = 0; j < 4; j++) {
            int idx = j * 256 + tid;        // 1024 = 8k x 128o
            int o = idx >> 3, k = idx & 7;
            if (k < kstage) {
                int ch = sidx[k];
                sW[k][o] = (ch >= 0) ? pw_w[(ob + o) * 128 + ch] : 0.f;
            }
        }
        // Y tile: one float4 per thread (256 = 8k x 32 f4)
        {
            int k = tid >> 5, f4 = tid & 31;
            if (k < kstage) {
                int ch = sidx[k];
                int hw = hwb + f4 * 4;
                float4 v = make_float4(0.f, 0.f, 0.f, 0.f);
                if (ch >= 0 && hw < 3136)
                    v = *(const float4*)(g_y + ((size_t)(b * 128 + ch)) * 3136 + hw);
                *(float4*)&sY[k][f4 * 4] = v;
            }
        }
        __syncthreads();

        for (int k0 = 0; k0 < klim; k0 += 4) {
#pragma unroll
            for (int ku = 0; ku < 4; ku++) {
                int k = k0 + ku;
                float4 A0 = *(const float4*)&sW[k][ty * 8];
                float4 A1 = *(const float4*)&sW[k][ty * 8 + 4];
                float4 B0 = *(const float4*)&sY[k][tx * 8];
                float4 B1 = *(const float4*)&sY[k][tx * 8 + 4];
                unsigned long long av[4];
                av[0] = pk2(A0.x, A0.y); av[1] = pk2(A0.z, A0.w);
                av[2] = pk2(A1.x, A1.y); av[3] = pk2(A1.z, A1.w);
                unsigned long long bq[8];
                bq[0] = pk2(B0.x, B0.x); bq[1] = pk2(B0.y, B0.y);
                bq[2] = pk2(B0.z, B0.z); bq[3] = pk2(B0.w, B0.w);
                bq[4] = pk2(B1.x, B1.x); bq[5] = pk2(B1.y, B1.y);
                bq[6] = pk2(B1.z, B1.z); bq[7] = pk2(B1.w, B1.w);
#pragma unroll
                for (int p = 0; p < 4; p++)
#pragma unroll
                    for (int q = 0; q < 8; q++)
                        acc[p][q] = fma2(av[p], bq[q], acc[p][q]);
            }
        }
        __syncthreads();
    }

    // epilogue: BN2 + ReLU + per-(b,o) max + store
#pragma unroll
    for (int r = 0; r < 8; r++) {
        int o = ob + ty * 8 + r;
        float sc = g2[o] * rsqrtf(v2[o] + EPSV);
        float tt = fmaf(pw_b[o] - m2[o], sc, b2[o]);
        float z[8];
        float m = 0.f;
#pragma unroll
        for (int q = 0; q < 8; q++) {
            float2 pr = upk2(acc[r >> 1][q]);
            float v = (r & 1) ? pr.y : pr.x;
            float zz = fmaxf(fmaf(v, sc, tt), 0.f);
            zz = colok ? zz : 0.f;
            z[q] = zz;
            m = fmaxf(m, zz);
        }
#pragma unroll
        for (int off = 1; off < 16; off <<= 1)
            m = fmaxf(m, __shfl_xor_sync(0xffffffffu, m, off));
        if (tx == 0) atomicMax(&g_max[b * 256 + o], __float_as_int(m));
        if (colok) {
            float* po = out + ((size_t)(b * 256 + o)) * 3136 + hwb + tx * 8;
            *(float4*)po       = make_float4(z[0], z[1], z[2], z[3]);
            *(float4*)(po + 4) = make_float4(z[4], z[5], z[6], z[7]);
        }
    }
}

// ---------------------------------------------------------------------------
// Final prune: zero (b,o) slices whose max < PW_THR.
// grid=4096, 4 slices/block; all 256 threads zero each failing slice.
// ---------------------------------------------------------------------------
__global__ __launch_bounds__(256) void prune_kernel(float* __restrict__ out) {
    const int s0 = blockIdx.x * 4;
    const int tid = threadIdx.x;
    __shared__ int fail[4];
    if (tid < 4)
        fail[tid] = (__int_as_float(g_max[s0 + tid]) < PW_THR) ? 1 : 0;
    __syncthreads();
    const float4 zz = make_float4(0.f, 0.f, 0.f, 0.f);
#pragma unroll
    for (int i = 0; i < 4; i++) {
        if (fail[i]) {
            float4* p4 = (float4*)(out + ((size_t)(s0 + i)) * 3136);
#pragma unroll
            for (int j = 0; j < 3; j++) {
                int idx = tid + j * 256;
                if (idx < 784) p4[idx] = zz;
            }
            if (tid + 768 < 784) p4[tid + 768] = zz;
        }
    }
}

// ---------------------------------------------------------------------------
extern "C" void kernel_launch(void* const* d_in, const int* in_sizes, int n_in,
                              void* d_out, int out_size)
{
    const float* x    = (const float*)d_in[0];
    const float* dw_w = (const float*)d_in[1];
    const float* dw_b = (const float*)d_in[2];
    const float* g1   = (const float*)d_in[3];
    const float* b1   = (const float*)d_in[4];
    const float* m1   = (const float*)d_in[5];
    const float* v1   = (const float*)d_in[6];
    const float* pw_w = (const float*)d_in[7];
    const float* pw_b = (const float*)d_in[8];
    const float* g2   = (const float*)d_in[9];
    const float* b2   = (const float*)d_in[10];
    const float* m2   = (const float*)d_in[11];
    const float* v2   = (const float*)d_in[12];
    float* out = (float*)d_out;

    dw_kernel<<<64 * 128, 256>>>(x, dw_w, dw_b, g1, b1, m1, v1);
    compact_kernel<<<64, 256>>>();
    pw_kernel<<<dim3(25, 2, 64), 256>>>(pw_w, pw_b, g2, b2, m2, v2, out);
    prune_kernel<<<4096, 256>>>(out);
}

// round 5
// speedup vs baseline: 1.0416x; 1.0416x over previous
#include <cuda_runtime.h>

#define EPSV   1e-5f
#define DW_THR 4.0f
#define PW_THR 0.001f

// Shapes: B=64, C=128, O=256, H=W=56, HW=3136
__device__ float g_y[64 * 128 * 3136];   // pruned depthwise output [B,C,HW]
__device__ int   g_keep[64 * 128];       // per-(b,c) keep flag
__device__ int   g_idx[64 * 128];        // per-b compacted kept-channel list
__device__ int   g_cnt[64];              // per-b kept count
__device__ int   g_max[64 * 256];        // per-(b,o) max(z) as int bits (z>=0)

// ---------------------------------------------------------------------------
// packed fp32x2 helpers (Blackwell FFMA2)
// ---------------------------------------------------------------------------
__device__ __forceinline__ unsigned long long fma2(unsigned long long a,
                                                   unsigned long long b,
                                                   unsigned long long c) {
    unsigned long long d;
    asm("fma.rn.f32x2 %0, %1, %2, %3;" : "=l"(d) : "l"(a), "l"(b), "l"(c));
    return d;
}
__device__ __forceinline__ unsigned long long pk2(float lo, float hi) {
    unsigned long long d;
    asm("mov.b64 %0, {%1, %2};" : "=l"(d) : "f"(lo), "f"(hi));
    return d;
}
__device__ __forceinline__ float2 upk2(unsigned long long v) {
    float2 r;
    asm("mov.b64 {%0, %1}, %2;" : "=f"(r.x), "=f"(r.y) : "l"(v));
    return r;
}

// ---------------------------------------------------------------------------
// Depthwise 3x3 + bias + BN1 + ReLU + per-(b,c) prune. (unchanged — passing)
// ---------------------------------------------------------------------------
__global__ __launch_bounds__(256) void dw_kernel(
    const float* __restrict__ x,
    const float* __restrict__ dw_w, const float* __restrict__ dw_b,
    const float* __restrict__ g1,  const float* __restrict__ b1,
    const float* __restrict__ m1,  const float* __restrict__ v1)
{
    __shared__ float sx[3136];
    __shared__ float red[8];
    __shared__ float s_bmax;

    const int slice = blockIdx.x;          // b*128 + c
    const int c = slice & 127;
    const float* xs = x + (size_t)slice * 3136;

    const float w0 = dw_w[c * 9 + 0], w1 = dw_w[c * 9 + 1], w2 = dw_w[c * 9 + 2];
    const float w3 = dw_w[c * 9 + 3], w4 = dw_w[c * 9 + 4], w5 = dw_w[c * 9 + 5];
    const float w6 = dw_w[c * 9 + 6], w7 = dw_w[c * 9 + 7], w8 = dw_w[c * 9 + 8];
    const float s = g1[c] * rsqrtf(v1[c] + EPSV);
    const float t = fmaf(dw_b[c] - m1[c], s, b1[c]);

    const int tid = threadIdx.x;

    {
        const float4* x4 = (const float4*)xs;
        float4* s4 = (float4*)sx;
        for (int i = tid; i < 784; i += 256) s4[i] = x4[i];
    }
    __syncthreads();

    float lv[14];
    float mx = 0.f;
    int col = 0, band = 0;
    if (tid < 224) {
        col  = tid % 56;
        band = tid / 56;               // rows band*14 .. band*14+13
        const bool cL = (col > 0), cR = (col < 55);
        const int base = band * 14 * 56 + col;

        float r0c0 = 0.f, r0c1 = 0.f, r0c2 = 0.f;
        if (band > 0) {
            int a = base - 56;
            r0c0 = cL ? sx[a - 1] : 0.f; r0c1 = sx[a]; r0c2 = cR ? sx[a + 1] : 0.f;
        }
        float r1c0 = cL ? sx[base - 1] : 0.f;
        float r1c1 = sx[base];
        float r1c2 = cR ? sx[base + 1] : 0.f;

#pragma unroll
        for (int j = 0; j < 14; j++) {
            int rr = band * 14 + j + 1;
            float r2c0 = 0.f, r2c1 = 0.f, r2c2 = 0.f;
            if (rr < 56) {
                int a = base + (j + 1) * 56;
                r2c0 = cL ? sx[a - 1] : 0.f; r2c1 = sx[a]; r2c2 = cR ? sx[a + 1] : 0.f;
            }
            float acc =        r0c0 * w0;
            acc = fmaf(r0c1, w1, acc); acc = fmaf(r0c2, w2, acc);
            acc = fmaf(r1c0, w3, acc); acc = fmaf(r1c1, w4, acc);
            acc = fmaf(r1c2, w5, acc);
            acc = fmaf(r2c0, w6, acc); acc = fmaf(r2c1, w7, acc);
            acc = fmaf(r2c2, w8, acc);
            float z = fmaxf(fmaf(acc, s, t), 0.f);
            lv[j] = z;
            mx = fmaxf(mx, z);
            r0c0 = r1c0; r0c1 = r1c1; r0c2 = r1c2;
            r1c0 = r2c0; r1c1 = r2c1; r1c2 = r2c2;
        }
    }

    for (int off = 16; off; off >>= 1)
        mx = fmaxf(mx, __shfl_xor_sync(0xffffffffu, mx, off));
    if ((tid & 31) == 0) red[tid >> 5] = mx;
    __syncthreads();
    if (tid == 0) {
        float m = red[0];
#pragma unroll
        for (int i = 1; i < 8; i++) m = fmaxf(m, red[i]);
        s_bmax = m;
        g_keep[slice] = (m >= DW_THR) ? 1 : 0;
    }
    __syncthreads();

    if (s_bmax >= DW_THR && tid < 224) {
        float* yo = g_y + (size_t)slice * 3136 + band * 14 * 56 + col;
#pragma unroll
        for (int j = 0; j < 14; j++) yo[j * 56] = lv[j];
    }
}

// ---------------------------------------------------------------------------
// Per-batch compaction of kept channels + zero g_max (graph-replay safe)
// ---------------------------------------------------------------------------
__global__ void compact_kernel() {
    const int b = blockIdx.x;
    const int tid = threadIdx.x;              // 256 threads
    g_max[b * 256 + tid] = 0;
    __shared__ int wcnt[4];
    if (tid < 128) {
        const int f = g_keep[b * 128 + tid];
        const unsigned bal = __ballot_sync(0xffffffffu, f);
        const int lane = tid & 31, w = tid >> 5;
        const int pre = __popc(bal & ((1u << lane) - 1u));
        if (lane == 0) wcnt[w] = __popc(bal);
        __syncthreads();
        int off = 0;
#pragma unroll
        for (int i = 0; i < 4; i++) if (i < w) off += wcnt[i];
        if (f) g_idx[b * 128 + off + pre] = tid;
        if (tid == 0) g_cnt[b] = wcnt[0] + wcnt[1] + wcnt[2] + wcnt[3];
    } else {
        __syncthreads();
    }
}

// ---------------------------------------------------------------------------
// Pointwise GEMM over compacted K + BN2 + ReLU + per-(b,o) max.
// Tile 128(O) x 64(HW) — 3136 = 64*49, NO tail. 8x4 microtile, FFMA2, KT=8.
// grid = (49, 2, 64), 256 threads, high occupancy for store MLP.
// ---------------------------------------------------------------------------
#define KT 8
__global__ __launch_bounds__(256, 4) void pw_kernel(
    const float* __restrict__ pw_w, const float* __restrict__ pw_b,
    const float* __restrict__ g2,  const float* __restrict__ b2,
    const float* __restrict__ m2,  const float* __restrict__ v2,
    float* __restrict__ out)
{
    __shared__ float sW[KT][132];   // [k][o]
    __shared__ float sY[KT][68];    // [k][hw]
    __shared__ int   sidx[KT];

    const int tid = threadIdx.x;
    const int tx = tid & 15;        // hw: 16 threads x 4
    const int ty = tid >> 4;        // o : 16 threads x 8
    const int hwb = blockIdx.x * 64;
    const int ob  = blockIdx.y * 128;
    const int b   = blockIdx.z;

    const int cnt = g_cnt[b];
    const int ntiles = (cnt + KT - 1) / KT;

    unsigned long long acc[4][4];
#pragma unroll
    for (int p = 0; p < 4; p++)
#pragma unroll
        for (int q = 0; q < 4; q++) acc[p][q] = 0ull;

    for (int kt = 0; kt < ntiles; kt++) {
        int klim = cnt - kt * KT;
        if (klim > KT) klim = KT;
        const int kstage = (klim + 3) & ~3;

        if (tid < KT) {
            int kk = kt * KT + tid;
            sidx[tid] = (kk < cnt) ? g_idx[b * 128 + kk] : -1;
        }
        __syncthreads();

        // W tile: gather+transpose -> sW[k][o], rows k < kstage
#pragma unroll
        for (int j = 0; j < 4; j++) {
            int idx = j * 256 + tid;        // 1024 = 8k x 128o
            int o = idx >> 3, k = idx & 7;
            if (k < kstage) {
                int ch = sidx[k];
                sW[k][o] = (ch >= 0) ? pw_w[(ob + o) * 128 + ch] : 0.f;
            }
        }
        // Y tile: 8k x 16 f4 = 128 threads
        if (tid < 128) {
            int k = tid >> 4, f4 = tid & 15;
            if (k < kstage) {
                int ch = sidx[k];
                float4 v = make_float4(0.f, 0.f, 0.f, 0.f);
                if (ch >= 0)
                    v = *(const float4*)(g_y + ((size_t)(b * 128 + ch)) * 3136 + hwb + f4 * 4);
                *(float4*)&sY[k][f4 * 4] = v;
            }
        }
        __syncthreads();

        for (int k0 = 0; k0 < klim; k0 += 4) {
#pragma unroll
            for (int ku = 0; ku < 4; ku++) {
                int k = k0 + ku;
                float4 A0 = *(const float4*)&sW[k][ty * 8];
                float4 A1 = *(const float4*)&sW[k][ty * 8 + 4];
                float4 B0 = *(const float4*)&sY[k][tx * 4];
                unsigned long long av[4];
                av[0] = pk2(A0.x, A0.y); av[1] = pk2(A0.z, A0.w);
                av[2] = pk2(A1.x, A1.y); av[3] = pk2(A1.z, A1.w);
                unsigned long long bq[4];
                bq[0] = pk2(B0.x, B0.x); bq[1] = pk2(B0.y, B0.y);
                bq[2] = pk2(B0.z, B0.z); bq[3] = pk2(B0.w, B0.w);
#pragma unroll
                for (int p = 0; p < 4; p++)
#pragma unroll
                    for (int q = 0; q < 4; q++)
                        acc[p][q] = fma2(av[p], bq[q], acc[p][q]);
            }
        }
        __syncthreads();
    }

    // epilogue: BN2 + ReLU + per-(b,o) max + store
#pragma unroll
    for (int r = 0; r < 8; r++) {
        int o = ob + ty * 8 + r;
        float sc = g2[o] * rsqrtf(v2[o] + EPSV);
        float tt = fmaf(pw_b[o] - m2[o], sc, b2[o]);
        float z[4];
        float m = 0.f;
#pragma unroll
        for (int q = 0; q < 4; q++) {
            float2 pr = upk2(acc[r >> 1][q]);
            float v = (r & 1) ? pr.y : pr.x;
            float zz = fmaxf(fmaf(v, sc, tt), 0.f);
            z[q] = zz;
            m = fmaxf(m, zz);
        }
#pragma unroll
        for (int off = 1; off < 16; off <<= 1)
            m = fmaxf(m, __shfl_xor_sync(0xffffffffu, m, off));
        if (tx == 0) atomicMax(&g_max[b * 256 + o], __float_as_int(m));
        float* po = out + ((size_t)(b * 256 + o)) * 3136 + hwb + tx * 4;
        *(float4*)po = make_float4(z[0], z[1], z[2], z[3]);
    }
}

// ---------------------------------------------------------------------------
// Final prune: one (b,o) slice per block; pass -> immediate exit (no sync).
// ---------------------------------------------------------------------------
__global__ __launch_bounds__(128) void prune_kernel(float* __restrict__ out) {
    const int slice = blockIdx.x;
    if (__int_as_float(g_max[slice]) >= PW_THR) return;   // warp-broadcast LDG
    const float4 zz = make_float4(0.f, 0.f, 0.f, 0.f);
    float4* p4 = (float4*)(out + (size_t)slice * 3136);
    const int tid = threadIdx.x;
#pragma unroll
    for (int j = 0; j < 6; j++) p4[tid + j * 128] = zz;   // 768
    if (tid < 16) p4[768 + tid] = zz;                      // 784
}

// ---------------------------------------------------------------------------
extern "C" void kernel_launch(void* const* d_in, const int* in_sizes, int n_in,
                              void* d_out, int out_size)
{
    const float* x    = (const float*)d_in[0];
    const float* dw_w = (const float*)d_in[1];
    const float* dw_b = (const float*)d_in[2];
    const float* g1   = (const float*)d_in[3];
    const float* b1   = (const float*)d_in[4];
    const float* m1   = (const float*)d_in[5];
    const float* v1   = (const float*)d_in[6];
    const float* pw_w = (const float*)d_in[7];
    const float* pw_b = (const float*)d_in[8];
    const float* g2   = (const float*)d_in[9];
    const float* b2   = (const float*)d_in[10];
    const float* m2   = (const float*)d_in[11];
    const float* v2   = (const float*)d_in[12];
    float* out = (float*)d_out;

    dw_kernel<<<64 * 128, 256>>>(x, dw_w, dw_b, g1, b1, m1, v1);
    compact_kernel<<<64, 256>>>();
    pw_kernel<<<dim3(49, 2, 64), 256>>>(pw_w, pw_b, g2, b2, m2, v2, out);
    prune_kernel<<<64 * 256, 128>>>(out);
}